// round 2
// baseline (speedup 1.0000x reference)
#include <cuda_runtime.h>
#include <cuda_bf16.h>
#include <math.h>

#define VOCAB   128
#define HIDDEN  1024
#define BATCH   64
#define SEQ     512

#define HSTRIDE 1026   // padded h-tile row stride (floats)
#define RSTRIDE 520    // padded reduce-buffer stride (floats, 8-byte aligned)
#define LOGITS_ELEMS (BATCH*SEQ*VOCAB)            // 4194304
#define SCAN_SMEM  ((1024*32 + 16*HSTRIDE) * 4)   // 196736 bytes

// ---------------- device scratch (static globals: no allocation) ----------------
__device__ float    g_embW[VOCAB * HIDDEN];              // emb @ W_hx + b_hx (512 KB)
__device__ float    g_hs[(size_t)SEQ * BATCH * HIDDEN];  // h_t for all steps (128 MB)
__device__ unsigned g_bar[8];                            // per-batch-group barrier

// ---------------- packed f32x2 helpers ----------------
typedef unsigned long long u64;

__device__ __forceinline__ u64 pack2(float x, float y) {
    u64 r;
    asm("mov.b64 %0, {%1, %2};" : "=l"(r) : "r"(__float_as_uint(x)), "r"(__float_as_uint(y)));
    return r;
}
__device__ __forceinline__ void unpack2(u64 v, float& x, float& y) {
    unsigned a, b;
    asm("mov.b64 {%0, %1}, %2;" : "=r"(a), "=r"(b) : "l"(v));
    x = __uint_as_float(a); y = __uint_as_float(b);
}
__device__ __forceinline__ void fma2(u64& acc, u64 a, u64 b) {
    asm("fma.rn.f32x2 %0, %1, %2, %0;" : "+l"(acc) : "l"(a), "l"(b));
}
__device__ __forceinline__ void add2(u64& acc, u64 v) {
    asm("add.rn.f32x2 %0, %0, %1;" : "+l"(acc) : "l"(v));
}
__device__ __forceinline__ unsigned ld_acquire(const unsigned* p) {
    unsigned v;
    asm volatile("ld.acquire.gpu.u32 %0, [%1];" : "=r"(v) : "l"(p));
    return v;
}

// ================================================================================
// Kernel 1: embW[v][n] = sum_k emb[v][k] * W_hx[k][n] + b_hx[n].
// 32 blocks x 256 threads: block = 4 vocab rows, thread = 4 output cols.
// Also resets the scan barrier counters (stream order guarantees visibility).
// ================================================================================
__global__ void __launch_bounds__(256)
embw_kernel(const float* __restrict__ emb,
            const float* __restrict__ W_hx,
            const float* __restrict__ b_hx)
{
    __shared__ float semb[4 * 1024];
    if (blockIdx.x == 0 && threadIdx.x < 8) g_bar[threadIdx.x] = 0u;

    const int tid = threadIdx.x;
    const int v0  = blockIdx.x * 4;

    for (int i = tid; i < 4096; i += 256)
        semb[i] = emb[(size_t)v0 * 1024 + i];
    __syncthreads();

    const int n0 = tid * 4;
    u64 acc[4][2];
    #pragma unroll
    for (int r = 0; r < 4; ++r) { acc[r][0] = 0ull; acc[r][1] = 0ull; }

    #pragma unroll 4
    for (int k = 0; k < 1024; ++k) {
        longlong2 wv = *(const longlong2*)&W_hx[(size_t)k * 1024 + n0];
        #pragma unroll
        for (int r = 0; r < 4; ++r) {
            float hv = semb[r * 1024 + k];
            u64 hh = pack2(hv, hv);
            fma2(acc[r][0], hh, (u64)wv.x);
            fma2(acc[r][1], hh, (u64)wv.y);
        }
    }

    float4 bx = *(const float4*)&b_hx[n0];
    #pragma unroll
    for (int r = 0; r < 4; ++r) {
        float a0, a1, a2, a3;
        unpack2(acc[r][0], a0, a1);
        unpack2(acc[r][1], a2, a3);
        *(float4*)&g_embW[(size_t)(v0 + r) * 1024 + n0] =
            make_float4(a0 + bx.x, a1 + bx.y, a2 + bx.z, a3 + bx.w);
    }
}

// ================================================================================
// Kernel 2: persistent RNN scan.
// 128 CTAs = 4 batch-groups (16 rows each) x 32 col-slices (32 cols each).
// W_hh col-slice (128 KB) SMEM-resident. Per step: stage h-tile from g_hs[t-1],
// 8-warp k-split GEMM (f32x2 FMA), SMEM reduce, + embW gather, tanh, write
// g_hs[t], spin-barrier among the 32 CTAs of the batch group.
// All 128 CTAs co-resident (1 CTA/SM at 197 KB smem, 128 <= 148 SMs): safe.
// ================================================================================
__global__ void __launch_bounds__(256, 1)
rnn_scan_kernel(const int*   __restrict__ x,
                const float* __restrict__ h0,
                const float* __restrict__ W_hh,
                float*       __restrict__ d_out,
                int out_size)
{
    extern __shared__ float smem[];
    float* Wsm = smem;                 // [1024][32]
    float* Hsm = smem + 1024 * 32;     // [16][HSTRIDE]; reused as reduce scratch
    __shared__ int sidx[16];

    const int tid = threadIdx.x;
    const int cta = blockIdx.x;
    const int gb  = cta >> 5;          // batch group 0..3
    const int gn  = cta & 31;          // column slice 0..31
    const int b0  = gb * 16;
    const int n0  = gn * 32;

    // Load W_hh[:, n0..n0+31] into SMEM (once per launch).
    for (int i = tid; i < 1024 * 8; i += 256) {
        int k = i >> 3, q = i & 7;
        float4 v = *(const float4*)&W_hh[(size_t)k * 1024 + n0 + q * 4];
        *(float4*)&Wsm[k * 32 + q * 4] = v;
    }

    const int lane  = tid & 31;
    const int w     = tid >> 5;        // warp 0..7 -> k range
    const int bg    = lane >> 3;       // 0..3 -> rows bg*4 .. bg*4+3
    const int ng    = lane & 7;        // 0..7 -> cols ng*4 .. ng*4+3
    const int kbase = w * 128;

    for (int t = 0; t < SEQ; ++t) {
        if (t > 0) {
            if (tid == 0) {
                unsigned tgt = 32u * (unsigned)t;
                while (ld_acquire(&g_bar[gb]) < tgt) { }
            }
            __syncthreads();   // also: prev-iter reduce reads done before restage
        }

        // Stage h tile: 16 rows x 1024 cols from h0 (t=0) or g_hs[t-1].
        const float* hsrc = (t == 0)
            ? (h0 + (size_t)b0 * 1024)
            : (g_hs + (size_t)(t - 1) * (BATCH * HIDDEN) + (size_t)b0 * 1024);
        for (int i = tid; i < 4096; i += 256) {
            int row = i >> 8, c4 = i & 255;
            float4 v = *(const float4*)&hsrc[(size_t)row * 1024 + c4 * 4];
            float* dst = &Hsm[row * HSTRIDE + c4 * 4];
            *(float2*)dst       = make_float2(v.x, v.y);
            *(float2*)(dst + 2) = make_float2(v.z, v.w);
        }
        if (tid < 16) sidx[tid] = x[(size_t)(b0 + tid) * SEQ + t];
        __syncthreads();

        // Partial GEMM over this warp's k range: 4b x 4n outputs per lane.
        u64 acc[4][2];
        #pragma unroll
        for (int i = 0; i < 4; ++i) { acc[i][0] = 0ull; acc[i][1] = 0ull; }

        const float* hb = &Hsm[(bg * 4) * HSTRIDE];
        #pragma unroll 4
        for (int k = kbase; k < kbase + 128; k += 2) {
            longlong2 wv0 = *(const longlong2*)&Wsm[k * 32 + ng * 4];
            longlong2 wv1 = *(const longlong2*)&Wsm[(k + 1) * 32 + ng * 4];
            #pragma unroll
            for (int i = 0; i < 4; ++i) {
                float2 h2 = *(const float2*)&hb[i * HSTRIDE + k];
                u64 hx = pack2(h2.x, h2.x);
                u64 hy = pack2(h2.y, h2.y);
                fma2(acc[i][0], hx, (u64)wv0.x);
                fma2(acc[i][1], hx, (u64)wv0.y);
                fma2(acc[i][0], hy, (u64)wv1.x);
                fma2(acc[i][1], hy, (u64)wv1.y);
            }
        }
        __syncthreads();   // Hsm reads done -> safe to reuse as reduce scratch

        float* red = Hsm;
        #pragma unroll
        for (int i = 0; i < 4; ++i) {
            int o = (bg * 4 + i) * 32 + ng * 4;
            *(u64*)&red[w * RSTRIDE + o]     = acc[i][0];
            *(u64*)&red[w * RSTRIDE + o + 2] = acc[i][1];
        }
        __syncthreads();

        // Reduce 8 warps, add input term, tanh, write h_t. 256 threads x 2 cols.
        {
            int o2 = tid * 2;
            u64 s = *(const u64*)&red[o2];
            #pragma unroll
            for (int ww = 1; ww < 8; ++ww)
                add2(s, *(const u64*)&red[ww * RSTRIDE + o2]);
            float s0, s1;
            unpack2(s, s0, s1);
            int b = o2 >> 5;        // 0..15
            int n = o2 & 31;        // even
            float2 e = *(const float2*)&g_embW[(size_t)sidx[b] * 1024 + n0 + n];
            float r0 = tanhf(s0 + e.x);
            float r1 = tanhf(s1 + e.y);
            *(float2*)&g_hs[(size_t)t * (BATCH * HIDDEN) + (size_t)(b0 + b) * 1024 + n0 + n]
                = make_float2(r0, r1);
            if (t == SEQ - 1 && out_size >= LOGITS_ELEMS + BATCH * HIDDEN) {
                *(float2*)&d_out[(size_t)LOGITS_ELEMS + (size_t)(b0 + b) * 1024 + n0 + n]
                    = make_float2(r0, r1);
            }
        }

        __threadfence();           // release h_t writes
        __syncthreads();
        if (tid == 0) atomicAdd(&g_bar[gb], 1u);
    }
}

// ================================================================================
// Kernel 3: logits[b][t][:] = g_hs[t][b][:] @ W_out + b_out.
// One CTA per timestep (A-tile = contiguous g_hs[t]). Tile 64x128, lane = 4r x 8c.
// ================================================================================
__global__ void __launch_bounds__(256)
logits_kernel(const float* __restrict__ W_out,
              const float* __restrict__ b_out,
              float*       __restrict__ out)
{
    __shared__ float Asm[64 * 17];
    __shared__ float Wsm[16 * 128];

    const int t   = blockIdx.x;
    const int tid = threadIdx.x;
    const int rg  = tid >> 4;      // 0..15 -> rows rg*4 .. +3
    const int cg  = tid & 15;      // 0..15 -> cols cg*8 .. +7

    u64 acc[4][4];
    #pragma unroll
    for (int i = 0; i < 4; ++i)
        #pragma unroll
        for (int j = 0; j < 4; ++j) acc[i][j] = 0ull;

    const float* A = g_hs + (size_t)t * (BATCH * HIDDEN);
    const int ar = tid >> 2;          // 0..63
    const int ac = (tid & 3) * 4;     // 0,4,8,12

    for (int k0 = 0; k0 < 1024; k0 += 16) {
        __syncthreads();
        {
            float4 av = *(const float4*)&A[(size_t)ar * 1024 + k0 + ac];
            Asm[ar * 17 + ac + 0] = av.x;
            Asm[ar * 17 + ac + 1] = av.y;
            Asm[ar * 17 + ac + 2] = av.z;
            Asm[ar * 17 + ac + 3] = av.w;
        }
        {
            const float* src = &W_out[(size_t)(k0 + rg) * 128 + cg * 8];
            float4 w0 = *(const float4*)&src[0];
            float4 w1 = *(const float4*)&src[4];
            *(float4*)&Wsm[rg * 128 + cg * 8]     = w0;
            *(float4*)&Wsm[rg * 128 + cg * 8 + 4] = w1;
        }
        __syncthreads();
        #pragma unroll
        for (int kk = 0; kk < 16; ++kk) {
            const float* wrow = &Wsm[kk * 128 + cg * 8];
            u64 w0 = *(const u64*)&wrow[0];
            u64 w1 = *(const u64*)&wrow[2];
            u64 w2 = *(const u64*)&wrow[4];
            u64 w3 = *(const u64*)&wrow[6];
            #pragma unroll
            for (int i = 0; i < 4; ++i) {
                float a = Asm[(rg * 4 + i) * 17 + kk];
                u64 aa = pack2(a, a);
                fma2(acc[i][0], aa, w0);
                fma2(acc[i][1], aa, w1);
                fma2(acc[i][2], aa, w2);
                fma2(acc[i][3], aa, w3);
            }
        }
    }

    float4 bv0 = *(const float4*)&b_out[cg * 8];
    float4 bv1 = *(const float4*)&b_out[cg * 8 + 4];
    #pragma unroll
    for (int i = 0; i < 4; ++i) {
        int row = rg * 4 + i;  // batch index
        float r0, r1, r2, r3, r4, r5, r6, r7;
        unpack2(acc[i][0], r0, r1);
        unpack2(acc[i][1], r2, r3);
        unpack2(acc[i][2], r4, r5);
        unpack2(acc[i][3], r6, r7);
        float* dst = &out[(size_t)row * (SEQ * VOCAB) + (size_t)t * VOCAB + cg * 8];
        *(float4*)dst       = make_float4(r0 + bv0.x, r1 + bv0.y, r2 + bv0.z, r3 + bv0.w);
        *(float4*)(dst + 4) = make_float4(r4 + bv1.x, r5 + bv1.y, r6 + bv1.z, r7 + bv1.w);
    }
}

// ================================================================================
extern "C" void kernel_launch(void* const* d_in, const int* in_sizes, int n_in,
                              void* d_out, int out_size)
{
    const int*   x     = (const int*)  d_in[0];
    const float* h     = (const float*)d_in[1];
    const float* emb   = (const float*)d_in[2];
    const float* W_hx  = (const float*)d_in[3];
    const float* b_hx  = (const float*)d_in[4];
    const float* W_hh  = (const float*)d_in[5];
    const float* W_out = (const float*)d_in[6];
    const float* b_out = (const float*)d_in[7];
    float*       out   = (float*)d_out;
    (void)in_sizes; (void)n_in;

    cudaFuncSetAttribute(rnn_scan_kernel,
                         cudaFuncAttributeMaxDynamicSharedMemorySize, SCAN_SMEM);

    embw_kernel<<<32, 256>>>(emb, W_hx, b_hx);
    rnn_scan_kernel<<<128, 256, SCAN_SMEM>>>(x, h, W_hh, out, out_size);
    logits_kernel<<<SEQ, 256>>>(W_out, b_out, out);
}